// round 11
// baseline (speedup 1.0000x reference)
#include <cuda_runtime.h>

// Modelev12: 2-layer LSTM, H=48, B=4096, T=512, F=64
// R10: two independent 256-thread clusters per CTA; within a cluster,
// warps split (k-half x row-half x batch-group) so each weight load serves
// 16 batches (4x less SMEM weight traffic than R6/R9). 4 warps/SMSP.
// Named per-cluster barriers; cluster 1 half-step skewed for phase overlap.
#define H      48
#define TOBS   512
#define FPRED  64
#define TTOT   (TOBS + FPRED)     // 576
#define BATCH  4096
#define MB     32                 // batch rows per CTA (16 per cluster)
#define NCTA   (BATCH / MB)       // 128
#define NTHR   512                // 16 warps = 2 clusters x (2kh x 2rh x 2bg)
#define NSKEW  1000               // ~4K cycle half-step skew for cluster 1

typedef unsigned long long ull;

__device__ unsigned int g_skew_sink[NCTA * NTHR];

// float-offset shared layout
#define OFF_WT0 0                         // [48][192]  Whh0^T
#define OFF_WT1 9216                      // [96][192]  [Wih1|Whh1]^T
#define OFF_WI0 27648                     // [192]
#define OFF_B0  27840                     // [192]
#define OFF_B1  28032                     // [192]
#define OFF_XC  28224                     // [2][16]
#define OFF_HC  28256                     // [2][96][16]  h state (batch-minor)
#define OFF_GT  31328                     // [2][192*17]  gates, stride 17
#define OFF_PB  (OFF_GT + 2*192*17)       // 37856: ull[8 slots][384] partials
#define SMEM_FLOATS (OFF_PB + 8*384*2)    // 44000 floats
#define SMEM_BYTES  (SMEM_FLOATS * 4)     // 176000 B

__device__ __forceinline__ ull ffma2(ull a, ull b, ull c) {
    ull d;
    asm("fma.rn.f32x2 %0, %1, %2, %3;" : "=l"(d) : "l"(a), "l"(b), "l"(c));
    return d;
}
__device__ __forceinline__ ull addf2(ull a, ull b) {
    ull d;
    asm("add.rn.f32x2 %0, %1, %2;" : "=l"(d) : "l"(a), "l"(b));
    return d;
}
__device__ __forceinline__ ull pack1(float v) {            // {v, v}
    ull d; asm("mov.b64 %0, {%1, %1};" : "=l"(d) : "f"(v)); return d;
}
__device__ __forceinline__ void unpack2(ull v, float& lo, float& hi) {
    asm("mov.b64 {%0, %1}, %2;" : "=f"(lo), "=f"(hi) : "l"(v));
}
__device__ __forceinline__ float fsig(float xv) {
    float e = __expf(-xv);
    return __fdividef(1.0f, 1.0f + e);
}
__device__ __forceinline__ float ftanh(float xv) {
    float a = fabsf(xv);
    float e = __expf(-2.0f * a);
    float r = __fdividef(1.0f - e, 1.0f + e);
    return copysignf(r, xv);
}
// per-cluster named barrier: 256 threads, id = cl+1
#define CBAR() asm volatile("bar.sync %0, 256;" :: "r"(cl + 1) : "memory")

__global__ void __launch_bounds__(NTHR, 1) lstm576_khsplit_kernel(
    const float* __restrict__ x,
    const float* __restrict__ wih0, const float* __restrict__ whh0,
    const float* __restrict__ bih0, const float* __restrict__ bhh0,
    const float* __restrict__ wih1, const float* __restrict__ whh1,
    const float* __restrict__ bih1, const float* __restrict__ bhh1,
    const float* __restrict__ wlin, const float* __restrict__ blin,
    float* __restrict__ out)
{
    extern __shared__ float sm[];
    float* WT0 = sm + OFF_WT0;
    float* WT1 = sm + OFF_WT1;
    float* WI0 = sm + OFF_WI0;
    float* B0s = sm + OFF_B0;
    float* B1s = sm + OFF_B1;

    const int tid  = threadIdx.x;
    const int lane = tid & 31;
    const int w    = tid >> 5;        // 0..15
    const int cl   = tid >> 8;        // cluster 0/1 (warps 0-7 | 8-15)
    const int tcl  = tid & 255;       // thread-in-cluster
    const int wc   = w & 7;           // warp-in-cluster
    const int kh   = wc & 1;          // k half
    const int rh   = (wc >> 1) & 1;   // row half: rows rh*96 .. +95
    const int bg   = wc >> 2;         // batch group: 8 batches
    const int rbase = rh * 96 + lane; // rows rbase, +32, +64
    const int gb0  = blockIdx.x * MB;

    float* XCc = sm + OFF_XC + cl * 16;
    float* HCc = sm + OFF_HC + cl * 96 * 16;     // HC[k][b], 16B-aligned rows
    float* GTc = sm + OFF_GT + cl * 192 * 17;    // GT[row*17 + b]
    ull*   PB  = (ull*)(sm + OFF_PB);
    ull*   PBs = PB + (cl * 4 + rh * 2 + bg) * 384;

    // head/act mappings
    const int hb  = tcl >> 3;         // head batch (tcl<128)
    const int m8h = tcl & 7;          // head k-chunk
    // act elements: e = tcl + 256*i; b = e&15, j = e>>4 (conflict-free h STS)
    int ebv[3], ejv[3];
#pragma unroll
    for (int i = 0; i < 3; i++) {
        int e = tcl + 256 * i;
        ebv[i] = e & 15; ejv[i] = e >> 4;
    }

    // ---- one-time staging ----
    for (int i = tid; i < 48 * 192; i += NTHR) {
        int k = i / 192, r = i - k * 192;
        WT0[i] = whh0[r * 48 + k];
    }
    for (int i = tid; i < 96 * 192; i += NTHR) {
        int k = i / 192, r = i - k * 192;
        WT1[i] = (k < 48) ? wih1[r * 48 + k] : whh1[r * 48 + (k - 48)];
    }
    for (int i = tid; i < 192; i += NTHR) {
        WI0[i] = wih0[i];
        B0s[i] = bih0[i] + bhh0[i];
        B1s[i] = bih1[i] + bhh1[i];
    }
    for (int i = tid; i < 2 * 96 * 16; i += NTHR) sm[OFF_HC + i] = 0.0f;
    if (tid < MB) sm[OFF_XC + tid] = x[(size_t)(gb0 + tid) * TOBS];
    const float blv = blin[0];

    float wlr[6];
#pragma unroll
    for (int i = 0; i < 6; i++) wlr[i] = wlin[m8h * 6 + i];

    float c0r[3], c1r[3];
#pragma unroll
    for (int i = 0; i < 3; i++) { c0r[i] = 0.0f; c1r[i] = 0.0f; }

    __syncthreads();   // staging done (only block-wide sync)

    // half-step skew for cluster 1 (clusters never re-converge)
    if (cl == 1) {
        unsigned int v = (unsigned int)(tid * 2654435761u + blockIdx.x);
#pragma unroll 1
        for (int i = 0; i < NSKEW; i++)
            v = v * 1664525u + 1013904223u;
        g_skew_sink[blockIdx.x * NTHR + tid] = v;
    }

    ull acc[3][4];

    for (int t = 0; t < TTOT; t++) {
        // prefetch next observed input (head-writer threads)
        float xnext = 0.0f;
        if (tcl < 128 && m8h == 0 && (t + 1) < TOBS)
            xnext = x[(size_t)(gb0 + cl * 16 + hb) * TOBS + (t + 1)];

        // ============ layer 0 matvec (k-half) ============
        {
            if (kh == 0) {   // bias + x term live in k-half 0
                ull x2[4];
                const float* xc = XCc + bg * 8;
#pragma unroll
                for (int bp = 0; bp < 4; bp++)
                    x2[bp] = *(const ull*)(xc + 2 * bp);
#pragma unroll
                for (int m = 0; m < 3; m++) {
                    ull wi = pack1(WI0[rbase + 32 * m]);
                    ull bs = pack1(B0s[rbase + 32 * m]);
#pragma unroll
                    for (int bp = 0; bp < 4; bp++)
                        acc[m][bp] = ffma2(wi, x2[bp], bs);
                }
            } else {
#pragma unroll
                for (int m = 0; m < 3; m++)
#pragma unroll
                    for (int bp = 0; bp < 4; bp++) acc[m][bp] = 0ull;
            }
            const int k0 = kh * 24;
#pragma unroll 4
            for (int g = 0; g < 12; g++) {
                int k = k0 + 2 * g;
                const ulonglong2* hp0 = (const ulonglong2*)(HCc + k * 16 + bg * 8);
                const ulonglong2* hp1 = (const ulonglong2*)(HCc + (k + 1) * 16 + bg * 8);
                ulonglong2 hA = hp0[0], hB = hp0[1];
                ulonglong2 hC = hp1[0], hD = hp1[1];
                float wa[3], wb[3];
#pragma unroll
                for (int m = 0; m < 3; m++) {
                    wa[m] = WT0[k * 192 + rbase + 32 * m];
                    wb[m] = WT0[(k + 1) * 192 + rbase + 32 * m];
                }
#pragma unroll
                for (int m = 0; m < 3; m++) {
                    ull w2 = pack1(wa[m]);
                    acc[m][0] = ffma2(w2, hA.x, acc[m][0]);
                    acc[m][1] = ffma2(w2, hA.y, acc[m][1]);
                    acc[m][2] = ffma2(w2, hB.x, acc[m][2]);
                    acc[m][3] = ffma2(w2, hB.y, acc[m][3]);
                }
#pragma unroll
                for (int m = 0; m < 3; m++) {
                    ull w2 = pack1(wb[m]);
                    acc[m][0] = ffma2(w2, hC.x, acc[m][0]);
                    acc[m][1] = ffma2(w2, hC.y, acc[m][1]);
                    acc[m][2] = ffma2(w2, hD.x, acc[m][2]);
                    acc[m][3] = ffma2(w2, hD.y, acc[m][3]);
                }
            }
            if (kh == 1) {   // publish partials
#pragma unroll
                for (int m = 0; m < 3; m++)
#pragma unroll
                    for (int bp = 0; bp < 4; bp++)
                        PBs[(m * 4 + bp) * 32 + lane] = acc[m][bp];
            }
        }
        CBAR();   // partials visible
        if (kh == 0) {   // merge + write gates (stride-17, conflict-free)
#pragma unroll
            for (int m = 0; m < 3; m++)
#pragma unroll
                for (int bp = 0; bp < 4; bp++) {
                    ull s2 = addf2(acc[m][bp], PBs[(m * 4 + bp) * 32 + lane]);
                    float g0, g1; unpack2(s2, g0, g1);
                    int r = rbase + 32 * m;
                    GTc[r * 17 + bg * 8 + 2 * bp]     = g0;
                    GTc[r * 17 + bg * 8 + 2 * bp + 1] = g1;
                }
        }
        CBAR();   // gates ready

        // ---- layer 0 activations ----
#pragma unroll
        for (int i = 0; i < 3; i++) {
            int b = ebv[i], j = ejv[i];
            const float* g = GTc + b;
            float ii = fsig(g[j * 17]);
            float ff = fsig(g[(j + 48) * 17]);
            float gg = ftanh(g[(j + 96) * 17]);
            float oo = fsig(g[(j + 144) * 17]);
            float c = fmaf(ff, c0r[i], ii * gg);
            c0r[i] = c;
            HCc[j * 16 + b] = oo * ftanh(c);
        }
        CBAR();   // h0 ready

        // ============ layer 1 matvec (k-half over h0|h1) ============
        {
            if (kh == 0) {
#pragma unroll
                for (int m = 0; m < 3; m++) {
                    ull bs = pack1(B1s[rbase + 32 * m]);
#pragma unroll
                    for (int bp = 0; bp < 4; bp++) acc[m][bp] = bs;
                }
            } else {
#pragma unroll
                for (int m = 0; m < 3; m++)
#pragma unroll
                    for (int bp = 0; bp < 4; bp++) acc[m][bp] = 0ull;
            }
            const int k0 = kh * 48;
#pragma unroll 4
            for (int g = 0; g < 24; g++) {
                int k = k0 + 2 * g;
                const ulonglong2* hp0 = (const ulonglong2*)(HCc + k * 16 + bg * 8);
                const ulonglong2* hp1 = (const ulonglong2*)(HCc + (k + 1) * 16 + bg * 8);
                ulonglong2 hA = hp0[0], hB = hp0[1];
                ulonglong2 hC = hp1[0], hD = hp1[1];
                float wa[3], wb[3];
#pragma unroll
                for (int m = 0; m < 3; m++) {
                    wa[m] = WT1[k * 192 + rbase + 32 * m];
                    wb[m] = WT1[(k + 1) * 192 + rbase + 32 * m];
                }
#pragma unroll
                for (int m = 0; m < 3; m++) {
                    ull w2 = pack1(wa[m]);
                    acc[m][0] = ffma2(w2, hA.x, acc[m][0]);
                    acc[m][1] = ffma2(w2, hA.y, acc[m][1]);
                    acc[m][2] = ffma2(w2, hB.x, acc[m][2]);
                    acc[m][3] = ffma2(w2, hB.y, acc[m][3]);
                }
#pragma unroll
                for (int m = 0; m < 3; m++) {
                    ull w2 = pack1(wb[m]);
                    acc[m][0] = ffma2(w2, hC.x, acc[m][0]);
                    acc[m][1] = ffma2(w2, hC.y, acc[m][1]);
                    acc[m][2] = ffma2(w2, hD.x, acc[m][2]);
                    acc[m][3] = ffma2(w2, hD.y, acc[m][3]);
                }
            }
            if (kh == 1) {
#pragma unroll
                for (int m = 0; m < 3; m++)
#pragma unroll
                    for (int bp = 0; bp < 4; bp++)
                        PBs[(m * 4 + bp) * 32 + lane] = acc[m][bp];
            }
        }
        CBAR();
        if (kh == 0) {
#pragma unroll
            for (int m = 0; m < 3; m++)
#pragma unroll
                for (int bp = 0; bp < 4; bp++) {
                    ull s2 = addf2(acc[m][bp], PBs[(m * 4 + bp) * 32 + lane]);
                    float g0, g1; unpack2(s2, g0, g1);
                    int r = rbase + 32 * m;
                    GTc[r * 17 + bg * 8 + 2 * bp]     = g0;
                    GTc[r * 17 + bg * 8 + 2 * bp + 1] = g1;
                }
        }
        CBAR();

        // ---- layer 1 activations ----
#pragma unroll
        for (int i = 0; i < 3; i++) {
            int b = ebv[i], j = ejv[i];
            const float* g = GTc + b;
            float ii = fsig(g[j * 17]);
            float ff = fsig(g[(j + 48) * 17]);
            float gg = ftanh(g[(j + 96) * 17]);
            float oo = fsig(g[(j + 144) * 17]);
            float c = fmaf(ff, c1r[i], ii * gg);
            c1r[i] = c;
            HCc[(48 + j) * 16 + b] = oo * ftanh(c);
        }
        CBAR();   // h1 ready

        // ---- output head: 8 threads per batch (tcl<128) ----
        if (tcl < 128) {
            float s = 0.0f;
            const float* h1 = HCc + 48 * 16 + hb;
#pragma unroll
            for (int i = 0; i < 6; i++)
                s = fmaf(h1[(m8h * 6 + i) * 16], wlr[i], s);
            s += __shfl_xor_sync(0xFFFFFFFFu, s, 1);
            s += __shfl_xor_sync(0xFFFFFFFFu, s, 2);
            s += __shfl_xor_sync(0xFFFFFFFFu, s, 4);
            if (m8h == 0) {
                s += blv;
                out[(size_t)(gb0 + cl * 16 + hb) * TTOT + t] = s;
                XCc[hb] = ((t + 1) < TOBS) ? xnext : s;
            }
        }
        CBAR();   // XC/out done -> next step
    }
}

extern "C" void kernel_launch(void* const* d_in, const int* in_sizes, int n_in,
                              void* d_out, int out_size)
{
    (void)in_sizes; (void)n_in; (void)out_size;
    const float* x    = (const float*)d_in[0];
    const float* wih0 = (const float*)d_in[1];
    const float* whh0 = (const float*)d_in[2];
    const float* bih0 = (const float*)d_in[3];
    const float* bhh0 = (const float*)d_in[4];
    const float* wih1 = (const float*)d_in[5];
    const float* whh1 = (const float*)d_in[6];
    const float* bih1 = (const float*)d_in[7];
    const float* bhh1 = (const float*)d_in[8];
    const float* wlin = (const float*)d_in[9];
    const float* blin = (const float*)d_in[10];
    float* out = (float*)d_out;

    cudaFuncSetAttribute(lstm576_khsplit_kernel,
                         cudaFuncAttributeMaxDynamicSharedMemorySize, SMEM_BYTES);
    lstm576_khsplit_kernel<<<NCTA, NTHR, SMEM_BYTES>>>(
        x, wih0, whh0, bih0, bhh0, wih1, whh1, bih1, bhh1, wlin, blin, out);
}

// round 12
// speedup vs baseline: 1.2177x; 1.2177x over previous
#include <cuda_runtime.h>

// Modelev12: 2-layer LSTM, H=48, B=4096, T=512, F=64
// R11 = R9 inner loop (warp-independent islands, f32x2, skew) re-tiled to use
// all 148 SMs: grid=147, 7 warps x 4 batches per CTA (last CTA: 2 warps).
// Per-SM L1 traffic -12.5%; busiest SMSP still 2 warps. No in-loop cross-warp
// sync (the thrice-confirmed requirement).
#define H      48
#define TOBS   512
#define FPRED  64
#define TTOT   (TOBS + FPRED)     // 576
#define BATCH  4096
#define MBC    28                 // batches per full CTA (7 warps x 4)
#define NCTA   147                // 146 full + 1 partial (8 batches)
#define NTHR   224                // 7 warps
#define NSKEW  1400               // ~5.6K-cycle half-step skew

typedef unsigned long long ull;

__device__ unsigned int g_skew_sink[NCTA * NTHR];   // unelidable skew sink

// float-offset shared layout (ull regions at even float offsets)
#define OFF_WTP0 0                       // ull[48*96]  {Whh0[q][k], Whh0[q+96][k]}
#define OFF_WTP1 9216                    // ull[96*96]  layer-1 row-paired
#define OFF_WI0P 27648                   // ull[96]
#define OFF_B0P  27840                   // ull[96]
#define OFF_B1P  28032                   // ull[96]
#define OFF_HW   28224                   // 7 warps x [96k][4b] floats (384 each)
#define OFF_XCW  (OFF_HW + 7*384)        // 7 warps x 8 floats
#define OFF_GTP  (OFF_XCW + 7*8)         // 7 warps x 4*GSTR ull
#define GSTR     101                     // ull stride per batch in gate buffer
#define GWARP    (4 * GSTR)
#define SMEM_FLOATS (OFF_GTP + 7 * 2 * GWARP)
#define SMEM_BYTES  (SMEM_FLOATS * 4)

__device__ __forceinline__ ull ffma2(ull a, ull b, ull c) {
    ull d;
    asm("fma.rn.f32x2 %0, %1, %2, %3;" : "=l"(d) : "l"(a), "l"(b), "l"(c));
    return d;
}
__device__ __forceinline__ ull pack1(float v) {            // {v, v}
    ull d; asm("mov.b64 %0, {%1, %1};" : "=l"(d) : "f"(v)); return d;
}
__device__ __forceinline__ ull pack2(float lo, float hi) {
    ull d; asm("mov.b64 %0, {%1, %2};" : "=l"(d) : "f"(lo), "f"(hi)); return d;
}
__device__ __forceinline__ float fsig(float xv) {
    float e = __expf(-xv);
    return __fdividef(1.0f, 1.0f + e);
}
__device__ __forceinline__ float ftanh(float xv) {
    float a = fabsf(xv);
    float e = __expf(-2.0f * a);
    float r = __fdividef(1.0f - e, 1.0f + e);
    return copysignf(r, xv);
}

__global__ void __launch_bounds__(NTHR, 1) lstm576_allsm_kernel(
    const float* __restrict__ x,
    const float* __restrict__ wih0, const float* __restrict__ whh0,
    const float* __restrict__ bih0, const float* __restrict__ bhh0,
    const float* __restrict__ wih1, const float* __restrict__ whh1,
    const float* __restrict__ bih1, const float* __restrict__ bhh1,
    const float* __restrict__ wlin, const float* __restrict__ blin,
    float* __restrict__ out)
{
    extern __shared__ float sm[];
    ull* WTP0 = (ull*)(sm + OFF_WTP0);
    ull* WTP1 = (ull*)(sm + OFF_WTP1);
    ull* WI0P = (ull*)(sm + OFF_WI0P);
    ull* B0P  = (ull*)(sm + OFF_B0P);
    ull* B1P  = (ull*)(sm + OFF_B1P);

    const int tid  = threadIdx.x;
    const int lane = tid & 31;
    const int w    = tid >> 5;           // warp 0..6
    const int m8   = lane & 7;           // 8-lane segment position
    const int lb   = lane >> 3;          // local batch 0..3
    const int gb0  = blockIdx.x * MBC;   // CTA batch base
    const int gbat = gb0 + 4 * w + lb;   // this lane's batch
    const bool active = (gb0 + 4 * w) < BATCH;   // warp has work?

    float* HWw  = sm + OFF_HW  + w * 384;            // [96][4] h state
    float* XCw  = sm + OFF_XCW + w * 8;              // 4 inputs
    ull*   GTPw = (ull*)(sm + OFF_GTP) + w * GWARP;  // [4][GSTR] gate pairs

    // ---- one-time staging (all warps participate) ----
    for (int i = tid; i < 48 * 96; i += NTHR) {
        int k = i / 96, q = i - k * 96;
        WTP0[i] = pack2(whh0[q * 48 + k], whh0[(q + 96) * 48 + k]);
    }
    for (int i = tid; i < 96 * 96; i += NTHR) {
        int k = i / 96, q = i - k * 96;
        float v0 = (k < 48) ? wih1[q * 48 + k] : whh1[q * 48 + (k - 48)];
        float v1 = (k < 48) ? wih1[(q + 96) * 48 + k] : whh1[(q + 96) * 48 + (k - 48)];
        WTP1[i] = pack2(v0, v1);
    }
    if (tid < 96) {
        WI0P[tid] = pack2(wih0[tid], wih0[tid + 96]);
        B0P[tid]  = pack2(bih0[tid] + bhh0[tid], bih0[tid + 96] + bhh0[tid + 96]);
        B1P[tid]  = pack2(bih1[tid] + bhh1[tid], bih1[tid + 96] + bhh1[tid + 96]);
    }
    for (int i = tid; i < 7 * 384; i += NTHR) sm[OFF_HW + i] = 0.0f;
    if (active && m8 == 0) XCw[lb] = x[(size_t)gbat * TOBS];
    const float blv = blin[0];

    float wlr[6];
#pragma unroll
    for (int i = 0; i < 6; i++) wlr[i] = wlin[m8 * 6 + i];

    float c0r[6], c1r[6];
#pragma unroll
    for (int i = 0; i < 6; i++) { c0r[i] = 0.0f; c1r[i] = 0.0f; }

    __syncthreads();   // staging done (only block-wide sync)
    if (!active) return;   // partial last CTA: warps 2..6 exit

    // anti-phase skew: second warp of SMSPs 0..2 delayed ~half a step
    if (w >= 4) {
        unsigned int v = (unsigned int)(tid * 2654435761u + blockIdx.x);
#pragma unroll 1
        for (int i = 0; i < NSKEW; i++)
            v = v * 1664525u + 1013904223u;      // dependent IMAD chain
        g_skew_sink[blockIdx.x * NTHR + tid] = v;
    }

    ull acc[3][4];

    for (int t = 0; t < TTOT; t++) {
        float xnext = 0.0f;
        if (m8 == 0 && (t + 1) < TOBS)
            xnext = x[(size_t)gbat * TOBS + (t + 1)];

        // ============ layer 0 matvec: 192 rows x (x + 48 h0) ============
        {
            float4 x4 = *(const float4*)XCw;
            ull xx[4] = { pack1(x4.x), pack1(x4.y), pack1(x4.z), pack1(x4.w) };
#pragma unroll
            for (int pp = 0; pp < 3; pp++) {
                ull wi = WI0P[32 * pp + lane];
                ull bs = B0P[32 * pp + lane];
#pragma unroll
                for (int b = 0; b < 4; b++) acc[pp][b] = ffma2(wi, xx[b], bs);
            }
#pragma unroll 4
            for (int kt = 0; kt < 48; kt += 4) {
                float4 hq[4];
#pragma unroll
                for (int d = 0; d < 4; d++)
                    hq[d] = *(const float4*)(HWw + (kt + d) * 4);
#pragma unroll
                for (int d = 0; d < 4; d++) {
                    ull w2[3];
#pragma unroll
                    for (int pp = 0; pp < 3; pp++)
                        w2[pp] = WTP0[(kt + d) * 96 + 32 * pp + lane];
                    ull hh[4] = { pack1(hq[d].x), pack1(hq[d].y),
                                  pack1(hq[d].z), pack1(hq[d].w) };
#pragma unroll
                    for (int pp = 0; pp < 3; pp++)
#pragma unroll
                        for (int b = 0; b < 4; b++)
                            acc[pp][b] = ffma2(w2[pp], hh[b], acc[pp][b]);
                }
            }
#pragma unroll
            for (int pp = 0; pp < 3; pp++)
#pragma unroll
                for (int b = 0; b < 4; b++)
                    GTPw[b * GSTR + 32 * pp + lane] = acc[pp][b];
        }
        __syncwarp();

        // ---- layer 0 activations: pair j = (i_j, g_j), pair j+48 = (f_j, o_j) ----
#pragma unroll
        for (int i = 0; i < 6; i++) {
            int j = m8 * 6 + i;
            float2 ig = *(const float2*)(GTPw + lb * GSTR + j);
            float2 fo = *(const float2*)(GTPw + lb * GSTR + 48 + j);
            float ii = fsig(ig.x), gg = ftanh(ig.y);
            float ff = fsig(fo.x), oo = fsig(fo.y);
            float c = fmaf(ff, c0r[i], ii * gg);
            c0r[i] = c;
            HWw[j * 4 + lb] = oo * ftanh(c);
        }
        __syncwarp();

        // ============ layer 1 matvec: 192 rows x (48 h0_new + 48 h1_old) ============
        {
#pragma unroll
            for (int pp = 0; pp < 3; pp++) {
                ull bs = B1P[32 * pp + lane];
#pragma unroll
                for (int b = 0; b < 4; b++) acc[pp][b] = bs;
            }
#pragma unroll 4
            for (int kt = 0; kt < 96; kt += 4) {
                float4 hq[4];
#pragma unroll
                for (int d = 0; d < 4; d++)
                    hq[d] = *(const float4*)(HWw + (kt + d) * 4);
#pragma unroll
                for (int d = 0; d < 4; d++) {
                    ull w2[3];
#pragma unroll
                    for (int pp = 0; pp < 3; pp++)
                        w2[pp] = WTP1[(kt + d) * 96 + 32 * pp + lane];
                    ull hh[4] = { pack1(hq[d].x), pack1(hq[d].y),
                                  pack1(hq[d].z), pack1(hq[d].w) };
#pragma unroll
                    for (int pp = 0; pp < 3; pp++)
#pragma unroll
                        for (int b = 0; b < 4; b++)
                            acc[pp][b] = ffma2(w2[pp], hh[b], acc[pp][b]);
                }
            }
#pragma unroll
            for (int pp = 0; pp < 3; pp++)
#pragma unroll
                for (int b = 0; b < 4; b++)
                    GTPw[b * GSTR + 32 * pp + lane] = acc[pp][b];
        }
        __syncwarp();

        // ---- layer 1 activations + fused in-warp head ----
        float s = 0.0f;
#pragma unroll
        for (int i = 0; i < 6; i++) {
            int j = m8 * 6 + i;
            float2 ig = *(const float2*)(GTPw + lb * GSTR + j);
            float2 fo = *(const float2*)(GTPw + lb * GSTR + 48 + j);
            float ii = fsig(ig.x), gg = ftanh(ig.y);
            float ff = fsig(fo.x), oo = fsig(fo.y);
            float c = fmaf(ff, c1r[i], ii * gg);
            c1r[i] = c;
            float h = oo * ftanh(c);
            HWw[(48 + j) * 4 + lb] = h;
            s = fmaf(h, wlr[i], s);
        }
        s += __shfl_xor_sync(0xFFFFFFFFu, s, 1);
        s += __shfl_xor_sync(0xFFFFFFFFu, s, 2);
        s += __shfl_xor_sync(0xFFFFFFFFu, s, 4);
        if (m8 == 0) {
            s += blv;
            out[(size_t)gbat * TTOT + t] = s;
            XCw[lb] = ((t + 1) < TOBS) ? xnext : s;
        }
        __syncwarp();
    }
}

extern "C" void kernel_launch(void* const* d_in, const int* in_sizes, int n_in,
                              void* d_out, int out_size)
{
    (void)in_sizes; (void)n_in; (void)out_size;
    const float* x    = (const float*)d_in[0];
    const float* wih0 = (const float*)d_in[1];
    const float* whh0 = (const float*)d_in[2];
    const float* bih0 = (const float*)d_in[3];
    const float* bhh0 = (const float*)d_in[4];
    const float* wih1 = (const float*)d_in[5];
    const float* whh1 = (const float*)d_in[6];
    const float* bih1 = (const float*)d_in[7];
    const float* bhh1 = (const float*)d_in[8];
    const float* wlin = (const float*)d_in[9];
    const float* blin = (const float*)d_in[10];
    float* out = (float*)d_out;

    cudaFuncSetAttribute(lstm576_allsm_kernel,
                         cudaFuncAttributeMaxDynamicSharedMemorySize, SMEM_BYTES);
    lstm576_allsm_kernel<<<NCTA, NTHR, SMEM_BYTES>>>(
        x, wih0, whh0, bih0, bhh0, wih1, whh1, bih1, bhh1, wlin, blin, out);
}